// round 16
// baseline (speedup 1.0000x reference)
#include <cuda_runtime.h>
#include <cuda_fp16.h>
#include <mma.h>
#include <math.h>
#include <stdint.h>

using namespace nvcuda;

#define D_ 1024
#define F_ 4096
#define E_ 8
#define T_ 4096
#define P_ (T_ * 2)

#define KB 64                     // K per chunk (elems)
#define ROWB 128                  // bytes per A smem row of data (64 fp16)
#define PITCH 144                 // smem row pitch bytes (bank-rotating)
#define PITCH_E 72                // pitch in fp16 elements
#define A_TILE (128 * PITCH)      // 18432 bytes
#define B_TILE (256 * PITCH)      // 36864 bytes
#define STAGE_SZ (A_TILE + B_TILE)      // 55296
#define CLD 264                   // epilogue float tile pitch (elements)
#define SMEM_TOTAL (128 * CLD * 4)      // 135168 >= 2*STAGE_SZ (110592)

#define CP_ASYNC16(dst, src) \
    asm volatile("cp.async.cg.shared.global [%0], [%1], 16;" :: "r"(dst), "l"(src) : "memory")
#define CP_COMMIT() asm volatile("cp.async.commit_group;" ::: "memory")
#define CP_WAIT0()  asm volatile("cp.async.wait_group 0;" ::: "memory")

__device__ __forceinline__ uint32_t smem_u32(const void* p) {
    uint32_t a;
    asm("{ .reg .u64 t; cvta.to.shared.u64 t, %1; cvt.u32.u64 %0, t; }" : "=r"(a) : "l"(p));
    return a;
}
__device__ __forceinline__ uint32_t pack2h(__half a, __half b) {
    return ((uint32_t)__half_as_ushort(b) << 16) | (uint32_t)__half_as_ushort(a);
}

// ---------------- device scratch ----------------
__device__ __half g_xgh[(size_t)P_ * D_];        // gathered x fp16
__device__ __half g_hh[(size_t)P_ * F_];         // gelu(h) fp16
__device__ float g_y[(size_t)P_ * D_];
__device__ int   g_top_e[T_ * 2];
__device__ float g_top_w[T_ * 2];
__device__ int   g_counts[E_];
__device__ int   g_offsets[E_];
__device__ int   g_pair_tok[P_];
__device__ float g_pair_w[P_];
__device__ int   g_slot_of[T_ * 2];

// ---------------- routing ----------------
__global__ void router_kernel(const float* __restrict__ x, const float* __restrict__ Wr) {
    int gw   = (blockIdx.x * blockDim.x + threadIdx.x) >> 5;
    int lane = threadIdx.x & 31;
    if (gw >= T_) return;
    const float* xt = x + (size_t)gw * D_;
    float acc[E_];
#pragma unroll
    for (int e = 0; e < E_; e++) acc[e] = 0.f;
    for (int d = lane; d < D_; d += 32) {
        float xv = xt[d];
#pragma unroll
        for (int e = 0; e < E_; e++) acc[e] += xv * Wr[e * D_ + d];
    }
#pragma unroll
    for (int e = 0; e < E_; e++) {
#pragma unroll
        for (int off = 16; off > 0; off >>= 1)
            acc[e] += __shfl_xor_sync(0xffffffffu, acc[e], off);
    }
    if (lane == 0) {
        float m = acc[0];
#pragma unroll
        for (int e = 1; e < E_; e++) m = fmaxf(m, acc[e]);
        float p[E_];
#pragma unroll
        for (int e = 0; e < E_; e++) p[e] = __expf(acc[e] - m);
        int e0 = 0; float v0 = p[0];
#pragma unroll
        for (int e = 1; e < E_; e++) if (p[e] > v0) { v0 = p[e]; e0 = e; }
        int e1 = (e0 == 0) ? 1 : 0; float v1 = p[e1];
#pragma unroll
        for (int e = 0; e < E_; e++) if (e != e0 && p[e] > v1) { v1 = p[e]; e1 = e; }
        float inv = 1.f / (v0 + v1);
        g_top_e[2 * gw]     = e0; g_top_w[2 * gw]     = v0 * inv;
        g_top_e[2 * gw + 1] = e1; g_top_w[2 * gw + 1] = v1 * inv;
    }
}

// single block: histogram + scan + fill
__global__ void route_build_kernel() {
    __shared__ int sc[E_], scur[E_];
    int tid = threadIdx.x;
    if (tid < E_) sc[tid] = 0;
    __syncthreads();
    for (int i = tid; i < P_; i += 256) atomicAdd(&sc[g_top_e[i]], 1);
    __syncthreads();
    if (tid == 0) {
        int o = 0;
        for (int e = 0; e < E_; e++) {
            g_offsets[e] = o; g_counts[e] = sc[e]; scur[e] = o; o += sc[e];
        }
    }
    __syncthreads();
    for (int i = tid; i < P_; i += 256) {
        int e = g_top_e[i];
        int slot = atomicAdd(&scur[e], 1);
        g_pair_tok[slot] = i >> 1;
        g_pair_w[slot]   = g_top_w[i];
        g_slot_of[i]     = slot;
    }
}

// gather tokens into slot order, fp16
__global__ void xgather_kernel(const float* __restrict__ x) {
    int i = blockIdx.x * blockDim.x + threadIdx.x;
    if (i >= P_ * D_ / 4) return;
    int slot = i / (D_ / 4);
    int c4   = i % (D_ / 4);
    int tok  = g_pair_tok[slot];
    float4 v = ((const float4*)(x + (size_t)tok * D_))[c4];
    ((uint2*)g_xgh)[i] = make_uint2(pack2h(__float2half(v.x), __float2half(v.y)),
                                    pack2h(__float2half(v.z), __float2half(v.w)));
}

// ================= WMMA fp16 single-pass GEMMs, fp32 B loaded direct =================
// CTA: 128(M)x256(N), K-chunk 64. 8 warps (2x4), warp tile 64x64, acc 4x4.
// A (fp16) via 2-stage cp.async; B (fp32 weights) via LDG.128 -> cvt -> STS,
// double-buffered through the barrier-released opposite stage. fp32 accum.
// Macro ends with fp32 tile in cbuf[128][CLD]; epilogue follows as plain code.

#define LDG_A(so, ko)                                                             \
    do {                                                                          \
        _Pragma("unroll")                                                         \
        for (int u = 0; u < 4; u++)                                               \
            CP_ASYNC16(adst[u] + (so), Ahp + aoffs[u] + (ko));                    \
        CP_COMMIT();                                                              \
    } while (0)

#define LDG_B(BSTR)                                                               \
    do {                                                                          \
        const char* _bp = Bfp + bko;                                              \
        _Pragma("unroll")                                                         \
        for (int u = 0; u < 16; u++)                                              \
            breg[u] = *(const float4*)(_bp + (size_t)u * (16 * (BSTR) * 4));      \
        bko += 256;                                                               \
    } while (0)

#define STS_B(so)                                                                 \
    do {                                                                          \
        _Pragma("unroll")                                                         \
        for (int u = 0; u < 16; u++) {                                            \
            uint2 hv;                                                             \
            hv.x = pack2h(__float2half(breg[u].x), __float2half(breg[u].y));      \
            hv.y = pack2h(__float2half(breg[u].z), __float2half(breg[u].w));      \
            *(uint2*)(smem + (so) + bs0 + u * (16 * PITCH)) = hv;                 \
        }                                                                         \
    } while (0)

#define GEMM_BODY(NCH, A_H, B_F32, A_STRIDE, B_STRIDE)                            \
    extern __shared__ char smem[];                                                \
    int tid = threadIdx.x;                                                        \
    int wid = tid >> 5, wm = wid >> 2, wn = wid & 3;                              \
    const char* Ahp = (const char*)(A_H);                                         \
    const char* Bfp;                                                              \
    size_t bko = 0;                                                               \
    uint32_t aoffs[4], adst[4], bs0;                                              \
    {                                                                             \
        uint32_t sb = smem_u32(smem);                                             \
        _Pragma("unroll")                                                         \
        for (int i = 0; i < 4; i++) {                                             \
            int lc = tid + i * 256;                                               \
            int r = lc >> 3, q = lc & 7;                                          \
            int gr = m0 + r; if (gr > count - 1) gr = count - 1;                  \
            aoffs[i] = (uint32_t)(base + gr) * (A_STRIDE) * 2 + q * 16;           \
            adst[i]  = sb + r * PITCH + q * 16;                                   \
        }                                                                         \
        int br = tid >> 4, bq = tid & 15;                                         \
        Bfp = (const char*)(B_F32) + (size_t)(n0 + br) * (B_STRIDE) * 4 + bq * 16;\
        bs0 = A_TILE + br * PITCH + bq * 8;                                       \
    }                                                                             \
    float4 breg[16];                                                              \
    wmma::fragment<wmma::accumulator, 16, 16, 16, float> acc[4][4];               \
    _Pragma("unroll")                                                             \
    for (int mt = 0; mt < 4; mt++)                                                \
        _Pragma("unroll")                                                         \
        for (int nt = 0; nt < 4; nt++) wmma::fill_fragment(acc[mt][nt], 0.0f);    \
    LDG_A(0, 0);                                                                  \
    LDG_B(B_STRIDE); STS_B(0);                                                    \
    LDG_B(B_STRIDE);                                                              \
    for (int i = 0; i < (NCH); i++) {                                             \
        CP_WAIT0();                                                               \
        __syncthreads();                                                          \
        if (i + 1 < (NCH)) {                                                      \
            uint32_t so = ((i + 1) & 1) * STAGE_SZ;                               \
            STS_B(so);                                                            \
            LDG_A(so, (size_t)(i + 1) * ROWB);                                    \
        }                                                                         \
        if (i + 2 < (NCH)) LDG_B(B_STRIDE);                                       \
        {                                                                         \
            const char* st = smem + (i & 1) * STAGE_SZ;                           \
            const __half* Ah = (const __half*)(st);                               \
            const __half* Bh = (const __half*)(st + A_TILE);                      \
            _Pragma("unroll")                                                     \
            for (int ks = 0; ks < 4; ks++) {                                      \
                wmma::fragment<wmma::matrix_b, 16, 16, 16, __half,                \
                               wmma::col_major> bf[4];                            \
                _Pragma("unroll")                                                 \
                for (int nt = 0; nt < 4; nt++)                                    \
                    wmma::load_matrix_sync(bf[nt],                                \
                        Bh + (wn * 64 + nt * 16) * PITCH_E + ks * 16, PITCH_E);   \
                wmma::fragment<wmma::matrix_a, 16, 16, 16, __half,                \
                               wmma::row_major> af[4];                            \
                _Pragma("unroll")                                                 \
                for (int mt = 0; mt < 4; mt++)                                    \
                    wmma::load_matrix_sync(af[mt],                                \
                        Ah + (wm * 64 + mt * 16) * PITCH_E + ks * 16, PITCH_E);   \
                _Pragma("unroll")                                                 \
                for (int mt = 0; mt < 4; mt++)                                    \
                    _Pragma("unroll")                                             \
                    for (int nt = 0; nt < 4; nt++)                                \
                        wmma::mma_sync(acc[mt][nt], af[mt], bf[nt], acc[mt][nt]); \
            }                                                                     \
        }                                                                         \
        __syncthreads();                                                          \
    }                                                                             \
    float* cbuf = (float*)smem;                                                   \
    _Pragma("unroll")                                                             \
    for (int mt = 0; mt < 4; mt++)                                                \
        _Pragma("unroll")                                                         \
        for (int nt = 0; nt < 4; nt++)                                            \
            wmma::store_matrix_sync(cbuf + (wm * 64 + mt * 16) * CLD + wn * 64 + nt * 16, \
                                    acc[mt][nt], CLD, wmma::mem_row_major);       \
    __syncthreads();

// GEMM1: h = gelu(xg @ W1[e]^T + b1[e]) -> fp16
__global__ void __launch_bounds__(256, 1) gemm1_mma(const float* __restrict__ W1,
                                                    const float* __restrict__ b1) {
    int e = blockIdx.z;
    int count = g_counts[e];
    int m0 = blockIdx.y * 128;
    if (m0 >= count) return;
    int base = g_offsets[e];
    int n0 = blockIdx.x * 256;

    GEMM_BODY(D_ / KB, g_xgh, W1 + (size_t)e * F_ * D_, D_, D_)

    const float* bp = b1 + (size_t)e * F_ + n0;
    for (int idx = tid; idx < 128 * 128; idx += 256) {
        int r = idx >> 7;
        int cp2 = idx & 127;
        int row = m0 + r;
        if (row >= count) continue;
        int col = cp2 * 2;
        float v0 = cbuf[r * CLD + col]     + bp[col];
        float v1 = cbuf[r * CLD + col + 1] + bp[col + 1];
        float g0 = 0.5f * v0 * (1.0f + erff(v0 * 0.70710678118654752440f));
        float g1 = 0.5f * v1 * (1.0f + erff(v1 * 0.70710678118654752440f));
        size_t ro = (size_t)(base + row) * F_ + n0;
        ((uint32_t*)(g_hh + ro))[cp2] = pack2h(__float2half(g0), __float2half(g1));
    }
}

// GEMM2: y = (h @ W2[e]^T + b2[e]) * w
__global__ void __launch_bounds__(256, 1) gemm2_mma(const float* __restrict__ W2,
                                                    const float* __restrict__ b2) {
    int e = blockIdx.z;
    int count = g_counts[e];
    int m0 = blockIdx.y * 128;
    if (m0 >= count) return;
    int base = g_offsets[e];
    int n0 = blockIdx.x * 256;

    GEMM_BODY(F_ / KB, g_hh, W2 + (size_t)e * D_ * F_, F_, F_)

    const float* bp = b2 + (size_t)e * D_ + n0;
    for (int idx = tid; idx < 128 * 128; idx += 256) {
        int r = idx >> 7;
        int cp2 = idx & 127;
        int row = m0 + r;
        if (row >= count) continue;
        int col = cp2 * 2;
        float w = g_pair_w[base + row];
        float v0 = (cbuf[r * CLD + col]     + bp[col])     * w;
        float v1 = (cbuf[r * CLD + col + 1] + bp[col + 1]) * w;
        float2 res;
        res.x = v0;
        res.y = v1;
        ((float2*)(g_y + (size_t)(base + row) * D_ + n0))[cp2] = res;
    }
}

// ---------------- combine ----------------
__global__ void combine_kernel(float* __restrict__ out) {
    int idx = blockIdx.x * blockDim.x + threadIdx.x;
    if (idx >= T_ * D_ / 4) return;
    int t  = idx / (D_ / 4);
    int c4 = idx % (D_ / 4);
    int s0 = g_slot_of[2 * t];
    int s1 = g_slot_of[2 * t + 1];
    float4 a = ((const float4*)(g_y + (size_t)s0 * D_))[c4];
    float4 b = ((const float4*)(g_y + (size_t)s1 * D_))[c4];
    float4 r;
    r.x = a.x + b.x; r.y = a.y + b.y; r.z = a.z + b.z; r.w = a.w + b.w;
    ((float4*)out)[idx] = r;
}

extern "C" void kernel_launch(void* const* d_in, const int* in_sizes, int n_in,
                              void* d_out, int out_size) {
    const float* x  = (const float*)d_in[0];
    const float* Wr = (const float*)d_in[1];
    const float* W1 = (const float*)d_in[2];
    const float* b1 = (const float*)d_in[3];
    const float* W2 = (const float*)d_in[4];
    const float* b2 = (const float*)d_in[5];
    float* out = (float*)d_out;

    cudaFuncSetAttribute(gemm1_mma, cudaFuncAttributeMaxDynamicSharedMemorySize, SMEM_TOTAL);
    cudaFuncSetAttribute(gemm2_mma, cudaFuncAttributeMaxDynamicSharedMemorySize, SMEM_TOTAL);

    router_kernel<<<(T_ * 32) / 256, 256>>>(x, Wr);                            // 1
    route_build_kernel<<<1, 256>>>();                                          // 2
    xgather_kernel<<<(P_ * D_ / 4) / 256, 256>>>(x);                           // 3

    dim3 g1(F_ / 256, T_ / 128, E_);   // (16, 32, 8)
    gemm1_mma<<<g1, 256, SMEM_TOTAL>>>(W1, b1);                                // 4

    dim3 g2(D_ / 256, T_ / 128, E_);   // (4, 32, 8)
    gemm2_mma<<<g2, 256, SMEM_TOTAL>>>(W2, b2);                                // 5

    combine_kernel<<<(T_ * D_ / 4) / 256, 256>>>(out);                         // 6
}

// round 17
// speedup vs baseline: 1.8126x; 1.8126x over previous
#include <cuda_runtime.h>
#include <cuda_fp16.h>
#include <mma.h>
#include <math.h>
#include <stdint.h>

using namespace nvcuda;

#define D_ 1024
#define F_ 4096
#define E_ 8
#define T_ 4096
#define P_ (T_ * 2)

#define KB 64                     // K per chunk (fp16 elems)
#define ROWB 128                  // bytes of data per smem row (64 fp16)
#define PITCH 144                 // smem row pitch bytes (bank-rotating)
#define PITCH_E 72                // pitch in fp16 elements
#define A_TILE (128 * PITCH)      // 18432 bytes
#define B_TILE (128 * PITCH)      // 18432 bytes
#define STAGE_SZ (A_TILE + B_TILE)      // 36864
#define NSTAGE 3
#define SMEM_TOTAL (NSTAGE * STAGE_SZ)  // 110592 -> 2 CTAs/SM
#define CLD 132                   // epilogue float tile pitch (elements)

#define CP_ASYNC16(dst, src) \
    asm volatile("cp.async.cg.shared.global [%0], [%1], 16;" :: "r"(dst), "l"(src) : "memory")
#define CP_COMMIT() asm volatile("cp.async.commit_group;" ::: "memory")
#define CP_WAIT2()  asm volatile("cp.async.wait_group 2;" ::: "memory")
#define CP_WAIT1()  asm volatile("cp.async.wait_group 1;" ::: "memory")
#define CP_WAIT0()  asm volatile("cp.async.wait_group 0;" ::: "memory")

__device__ __forceinline__ uint32_t smem_u32(const void* p) {
    uint32_t a;
    asm("{ .reg .u64 t; cvta.to.shared.u64 t, %1; cvt.u32.u64 %0, t; }" : "=r"(a) : "l"(p));
    return a;
}
__device__ __forceinline__ uint32_t pack2h(__half a, __half b) {
    return ((uint32_t)__half_as_ushort(b) << 16) | (uint32_t)__half_as_ushort(a);
}

// ---------------- device scratch ----------------
__device__ __half g_w1h[(size_t)E_ * F_ * D_];   // W1 fp16
__device__ __half g_w2h[(size_t)E_ * D_ * F_];   // W2 fp16
__device__ __half g_xgh[(size_t)P_ * D_];        // gathered x fp16
__device__ __half g_hh[(size_t)P_ * F_];         // gelu(h) fp16
__device__ float g_y[(size_t)P_ * D_];
__device__ int   g_top_e[T_ * 2];
__device__ float g_top_w[T_ * 2];
__device__ int   g_counts[E_];
__device__ int   g_offsets[E_];
__device__ int   g_pair_tok[P_];
__device__ float g_pair_w[P_];
__device__ int   g_slot_of[T_ * 2];

// ---------------- routing ----------------
__global__ void router_kernel(const float* __restrict__ x, const float* __restrict__ Wr) {
    int gw   = (blockIdx.x * blockDim.x + threadIdx.x) >> 5;
    int lane = threadIdx.x & 31;
    if (gw >= T_) return;
    const float* xt = x + (size_t)gw * D_;
    float acc[E_];
#pragma unroll
    for (int e = 0; e < E_; e++) acc[e] = 0.f;
    for (int d = lane; d < D_; d += 32) {
        float xv = xt[d];
#pragma unroll
        for (int e = 0; e < E_; e++) acc[e] += xv * Wr[e * D_ + d];
    }
#pragma unroll
    for (int e = 0; e < E_; e++) {
#pragma unroll
        for (int off = 16; off > 0; off >>= 1)
            acc[e] += __shfl_xor_sync(0xffffffffu, acc[e], off);
    }
    if (lane == 0) {
        float m = acc[0];
#pragma unroll
        for (int e = 1; e < E_; e++) m = fmaxf(m, acc[e]);
        float p[E_];
#pragma unroll
        for (int e = 0; e < E_; e++) p[e] = __expf(acc[e] - m);
        int e0 = 0; float v0 = p[0];
#pragma unroll
        for (int e = 1; e < E_; e++) if (p[e] > v0) { v0 = p[e]; e0 = e; }
        int e1 = (e0 == 0) ? 1 : 0; float v1 = p[e1];
#pragma unroll
        for (int e = 0; e < E_; e++) if (e != e0 && p[e] > v1) { v1 = p[e]; e1 = e; }
        float inv = 1.f / (v0 + v1);
        g_top_e[2 * gw]     = e0; g_top_w[2 * gw]     = v0 * inv;
        g_top_e[2 * gw + 1] = e1; g_top_w[2 * gw + 1] = v1 * inv;
    }
}

// single block: histogram + scan + fill
__global__ void route_build_kernel() {
    __shared__ int sc[E_], scur[E_];
    int tid = threadIdx.x;
    if (tid < E_) sc[tid] = 0;
    __syncthreads();
    for (int i = tid; i < P_; i += 256) atomicAdd(&sc[g_top_e[i]], 1);
    __syncthreads();
    if (tid == 0) {
        int o = 0;
        for (int e = 0; e < E_; e++) {
            g_offsets[e] = o; g_counts[e] = sc[e]; scur[e] = o; o += sc[e];
        }
    }
    __syncthreads();
    for (int i = tid; i < P_; i += 256) {
        int e = g_top_e[i];
        int slot = atomicAdd(&scur[e], 1);
        g_pair_tok[slot] = i >> 1;
        g_pair_w[slot]   = g_top_w[i];
        g_slot_of[i]     = slot;
    }
}

// ---------------- fp32 -> fp16 (weights) ----------------
__global__ void split_kernel(const float4* __restrict__ src, uint2* __restrict__ dh, int n4) {
    int i = blockIdx.x * blockDim.x + threadIdx.x;
    if (i >= n4) return;
    float4 v = src[i];
    dh[i] = make_uint2(pack2h(__float2half(v.x), __float2half(v.y)),
                       pack2h(__float2half(v.z), __float2half(v.w)));
}

// gather tokens into slot order, fp16
__global__ void xgather_kernel(const float* __restrict__ x) {
    int i = blockIdx.x * blockDim.x + threadIdx.x;
    if (i >= P_ * D_ / 4) return;
    int slot = i / (D_ / 4);
    int c4   = i % (D_ / 4);
    int tok  = g_pair_tok[slot];
    float4 v = ((const float4*)(x + (size_t)tok * D_))[c4];
    ((uint2*)g_xgh)[i] = make_uint2(pack2h(__float2half(v.x), __float2half(v.y)),
                                    pack2h(__float2half(v.z), __float2half(v.w)));
}

// ================= WMMA fp16 single-pass GEMMs =================
// CTA: 128(M)x128(N), K-chunk 64. 8 warps (2x4), warp tile 64x32, acc 4x2.
// 3-stage cp.async pipeline; __launch_bounds__(256,2) -> 2 CTAs/SM.
// Macro ends with fp32 tile in cbuf[128][CLD]; epilogue follows as plain code.

#define LDG_ALL(so, ko)                                                           \
    do {                                                                          \
        _Pragma("unroll")                                                         \
        for (int u = 0; u < 4; u++)                                               \
            CP_ASYNC16(adst[u] + (so), Ahp + aoffs[u] + (ko));                    \
        _Pragma("unroll")                                                         \
        for (int u = 0; u < 4; u++)                                               \
            CP_ASYNC16(adst[u] + A_TILE + (so), Bhp + boffs[u] + (ko));           \
    } while (0)

#define GEMM_BODY(NCH, A_H, B_H, A_STRIDE, B_STRIDE)                              \
    extern __shared__ char smem[];                                                \
    int tid = threadIdx.x;                                                        \
    int wid = tid >> 5, wm = wid >> 2, wn = wid & 3;                              \
    const char* Ahp = (const char*)(A_H);                                         \
    const char* Bhp = (const char*)(B_H);                                         \
    uint32_t aoffs[4], boffs[4], adst[4];                                         \
    {                                                                             \
        uint32_t sb = smem_u32(smem);                                             \
        _Pragma("unroll")                                                         \
        for (int i = 0; i < 4; i++) {                                             \
            int lc = tid + i * 256;                                               \
            int r = lc >> 3, q = lc & 7;                                          \
            int gr = m0 + r; if (gr > count - 1) gr = count - 1;                  \
            aoffs[i] = (uint32_t)(base + gr) * (A_STRIDE) * 2 + q * 16;           \
            boffs[i] = (uint32_t)(n0 + r) * (B_STRIDE) * 2 + q * 16;              \
            adst[i]  = sb + r * PITCH + q * 16;                                   \
        }                                                                         \
    }                                                                             \
    wmma::fragment<wmma::accumulator, 16, 16, 16, float> acc[4][2];               \
    _Pragma("unroll")                                                             \
    for (int mt = 0; mt < 4; mt++)                                                \
        _Pragma("unroll")                                                         \
        for (int nt = 0; nt < 2; nt++) wmma::fill_fragment(acc[mt][nt], 0.0f);    \
    LDG_ALL(0, 0); CP_COMMIT();                                                   \
    LDG_ALL(STAGE_SZ, ROWB); CP_COMMIT();                                         \
    for (int i = 0; i < (NCH); i++) {                                             \
        if (i + 2 < (NCH)) {                                                      \
            uint32_t so = ((i + 2) % NSTAGE) * STAGE_SZ;                          \
            size_t ko = (size_t)(i + 2) * ROWB;                                   \
            LDG_ALL(so, ko); CP_COMMIT(); CP_WAIT2();                             \
        } else if (i + 1 < (NCH)) {                                               \
            CP_WAIT1();                                                           \
        } else {                                                                  \
            CP_WAIT0();                                                           \
        }                                                                         \
        __syncthreads();                                                          \
        {                                                                         \
            const char* st = smem + (i % NSTAGE) * STAGE_SZ;                      \
            const __half* Ah = (const __half*)(st);                               \
            const __half* Bh = (const __half*)(st + A_TILE);                      \
            _Pragma("unroll")                                                     \
            for (int ks = 0; ks < 4; ks++) {                                      \
                wmma::fragment<wmma::matrix_b, 16, 16, 16, __half,                \
                               wmma::col_major> bf[2];                            \
                _Pragma("unroll")                                                 \
                for (int nt = 0; nt < 2; nt++)                                    \
                    wmma::load_matrix_sync(bf[nt],                                \
                        Bh + (wn * 32 + nt * 16) * PITCH_E + ks * 16, PITCH_E);   \
                wmma::fragment<wmma::matrix_a, 16, 16, 16, __half,                \
                               wmma::row_major> af[4];                            \
                _Pragma("unroll")                                                 \
                for (int mt = 0; mt < 4; mt++)                                    \
                    wmma::load_matrix_sync(af[mt],                                \
                        Ah + (wm * 64 + mt * 16) * PITCH_E + ks * 16, PITCH_E);   \
                _Pragma("unroll")                                                 \
                for (int mt = 0; mt < 4; mt++)                                    \
                    _Pragma("unroll")                                             \
                    for (int nt = 0; nt < 2; nt++)                                \
                        wmma::mma_sync(acc[mt][nt], af[mt], bf[nt], acc[mt][nt]); \
            }                                                                     \
        }                                                                         \
        __syncthreads();                                                          \
    }                                                                             \
    float* cbuf = (float*)smem;                                                   \
    _Pragma("unroll")                                                             \
    for (int mt = 0; mt < 4; mt++)                                                \
        _Pragma("unroll")                                                         \
        for (int nt = 0; nt < 2; nt++)                                            \
            wmma::store_matrix_sync(cbuf + (wm * 64 + mt * 16) * CLD + wn * 32 + nt * 16, \
                                    acc[mt][nt], CLD, wmma::mem_row_major);       \
    __syncthreads();

// GEMM1: h = gelu(xg @ W1[e]^T + b1[e]) -> fp16
__global__ void __launch_bounds__(256, 2) gemm1_mma(const float* __restrict__ b1) {
    int e = blockIdx.z;
    int count = g_counts[e];
    int m0 = blockIdx.y * 128;
    if (m0 >= count) return;
    int base = g_offsets[e];
    int n0 = blockIdx.x * 128;

    GEMM_BODY(D_ / KB, g_xgh, g_w1h + (size_t)e * F_ * D_, D_, D_)

    const float* bp = b1 + (size_t)e * F_ + n0;
    for (int idx = tid; idx < 128 * 64; idx += 256) {
        int r = idx >> 6;
        int cp2 = idx & 63;
        int row = m0 + r;
        if (row >= count) continue;
        int col = cp2 * 2;
        float v0 = cbuf[r * CLD + col]     + bp[col];
        float v1 = cbuf[r * CLD + col + 1] + bp[col + 1];
        float g0 = 0.5f * v0 * (1.0f + erff(v0 * 0.70710678118654752440f));
        float g1 = 0.5f * v1 * (1.0f + erff(v1 * 0.70710678118654752440f));
        size_t ro = (size_t)(base + row) * F_ + n0;
        ((uint32_t*)(g_hh + ro))[cp2] = pack2h(__float2half(g0), __float2half(g1));
    }
}

// GEMM2: y = (h @ W2[e]^T + b2[e]) * w
__global__ void __launch_bounds__(256, 2) gemm2_mma(const float* __restrict__ b2) {
    int e = blockIdx.z;
    int count = g_counts[e];
    int m0 = blockIdx.y * 128;
    if (m0 >= count) return;
    int base = g_offsets[e];
    int n0 = blockIdx.x * 128;

    GEMM_BODY(F_ / KB, g_hh, g_w2h + (size_t)e * D_ * F_, F_, F_)

    const float* bp = b2 + (size_t)e * D_ + n0;
    for (int idx = tid; idx < 128 * 64; idx += 256) {
        int r = idx >> 6;
        int cp2 = idx & 63;
        int row = m0 + r;
        if (row >= count) continue;
        int col = cp2 * 2;
        float w = g_pair_w[base + row];
        float v0 = (cbuf[r * CLD + col]     + bp[col])     * w;
        float v1 = (cbuf[r * CLD + col + 1] + bp[col + 1]) * w;
        float2 res;
        res.x = v0;
        res.y = v1;
        ((float2*)(g_y + (size_t)(base + row) * D_ + n0))[cp2] = res;
    }
}

// ---------------- combine ----------------
__global__ void combine_kernel(float* __restrict__ out) {
    int idx = blockIdx.x * blockDim.x + threadIdx.x;
    if (idx >= T_ * D_ / 4) return;
    int t  = idx / (D_ / 4);
    int c4 = idx % (D_ / 4);
    int s0 = g_slot_of[2 * t];
    int s1 = g_slot_of[2 * t + 1];
    float4 a = ((const float4*)(g_y + (size_t)s0 * D_))[c4];
    float4 b = ((const float4*)(g_y + (size_t)s1 * D_))[c4];
    float4 r;
    r.x = a.x + b.x; r.y = a.y + b.y; r.z = a.z + b.z; r.w = a.w + b.w;
    ((float4*)out)[idx] = r;
}

extern "C" void kernel_launch(void* const* d_in, const int* in_sizes, int n_in,
                              void* d_out, int out_size) {
    const float* x  = (const float*)d_in[0];
    const float* Wr = (const float*)d_in[1];
    const float* W1 = (const float*)d_in[2];
    const float* b1 = (const float*)d_in[3];
    const float* W2 = (const float*)d_in[4];
    const float* b2 = (const float*)d_in[5];
    float* out = (float*)d_out;

    cudaFuncSetAttribute(gemm1_mma, cudaFuncAttributeMaxDynamicSharedMemorySize, SMEM_TOTAL);
    cudaFuncSetAttribute(gemm2_mma, cudaFuncAttributeMaxDynamicSharedMemorySize, SMEM_TOTAL);

    __half *w1h, *w2h;
    cudaGetSymbolAddress((void**)&w1h, g_w1h);
    cudaGetSymbolAddress((void**)&w2h, g_w2h);

    int wn4 = E_ * F_ * D_ / 4;
    split_kernel<<<wn4 / 256, 256>>>((const float4*)W1, (uint2*)w1h, wn4);     // 1
    split_kernel<<<wn4 / 256, 256>>>((const float4*)W2, (uint2*)w2h, wn4);     // 2
    router_kernel<<<(T_ * 32) / 256, 256>>>(x, Wr);                            // 3
    route_build_kernel<<<1, 256>>>();                                          // 4
    xgather_kernel<<<(P_ * D_ / 4) / 256, 256>>>(x);                           // 5

    dim3 g1(F_ / 128, T_ / 128, E_);   // (32, 32, 8)
    gemm1_mma<<<g1, 256, SMEM_TOTAL>>>(b1);                                    // 6 <- ncu

    dim3 g2(D_ / 128, T_ / 128, E_);   // (8, 32, 8)
    gemm2_mma<<<g2, 256, SMEM_TOTAL>>>(b2);                                    // 7

    combine_kernel<<<(T_ * D_ / 4) / 256, 256>>>(out);                         // 8
}